// round 8
// baseline (speedup 1.0000x reference)
#include <cuda_runtime.h>
#include <cstdint>
#include <math_constants.h>

constexpr int BATCH = 4, SEQ = 2048, DIM = 1024, MTOT = BATCH * SEQ;
typedef signed char i8;

// ---- scratch (device globals) ----
__device__ __align__(16) i8    g_X1[(size_t)MTOT*DIM], g_X2[(size_t)MTOT*DIM];
__device__ float g_sX[MTOT];
__device__ __align__(16) float g_Wt[(size_t)4*DIM*DIM];
__device__ __align__(16) i8    g_W1[(size_t)4*DIM*DIM], g_W2[(size_t)4*DIM*DIM];
__device__ float g_sW[4*DIM];
__device__ __align__(16) float g_Qf[(size_t)MTOT*DIM], g_Kf[(size_t)MTOT*DIM];
__device__ __align__(16) float g_Vtf[(size_t)BATCH*DIM*SEQ];
__device__ __align__(16) i8    g_Q1[(size_t)MTOT*DIM], g_Q2[(size_t)MTOT*DIM];
__device__ float g_sQ[MTOT];
__device__ __align__(16) i8    g_K1[(size_t)MTOT*DIM], g_K2[(size_t)MTOT*DIM];
__device__ float g_sK[MTOT];
__device__ __align__(16) i8    g_V1[(size_t)BATCH*DIM*SEQ], g_V2[(size_t)BATCH*DIM*SEQ];
__device__ float g_sV[BATCH*DIM];
__device__ __align__(16) float g_S[(size_t)BATCH*SEQ*SEQ];
__device__ __align__(16) i8    g_P1[(size_t)BATCH*SEQ*SEQ], g_P2[(size_t)BATCH*SEQ*SEQ];
__device__ float g_sP[BATCH*SEQ];
__device__ __align__(16) float g_Of[(size_t)MTOT*DIM];
__device__ __align__(16) i8    g_O1[(size_t)MTOT*DIM], g_O2[(size_t)MTOT*DIM];
__device__ float g_sO[MTOT];

__device__ __forceinline__ uint32_t s2u(const void* p) {
    uint32_t a;
    asm("{ .reg .u64 t; cvta.to.shared.u64 t, %1; cvt.u32.u64 %0, t; }" : "=r"(a) : "l"(p));
    return a;
}
#define CPA16(dst, src) \
    asm volatile("cp.async.cg.shared.global [%0], [%1], 16;" :: "r"(dst), "l"(src) : "memory")
#define LDSM4(r, a) \
    asm volatile("ldmatrix.sync.aligned.m8n8.x4.shared.b16 {%0,%1,%2,%3}, [%4];" \
        : "=r"((r)[0]), "=r"((r)[1]), "=r"((r)[2]), "=r"((r)[3]) : "r"(a))
#define MMAI8(c, a, b0, b1) \
    asm volatile("mma.sync.aligned.m16n8k32.row.col.s32.s8.s8.s32 " \
        "{%0,%1,%2,%3}, {%4,%5,%6,%7}, {%8,%9}, {%0,%1,%2,%3};" \
        : "+r"((c)[0]), "+r"((c)[1]), "+r"((c)[2]), "+r"((c)[3]) \
        : "r"((a)[0]), "r"((a)[1]), "r"((a)[2]), "r"((a)[3]), "r"(b0), "r"(b1))

// ---- int8 GEMM: C[m][n] = alpha*sA[m]*sB[n]*(65536*A1B1 + 256*(A1B2+A2B1)) ----
// CTA 128x128, 8 warps (2x4), warp tile 64x32, K-chunk 32, 4-stage cp.async.
// SMEM rows 48B (ldmatrix bank-perm r*12 mod 32 conflict-free).
constexpr int ROWB = 48;
constexpr int R_A1 = 0, R_A2 = 6144, R_B1 = 12288, R_B2 = 18432;
constexpr int STAGE_SZ = 24576, NSTAGE = 4, GEMM_SMEM = 98304;

template<bool TRANSOUT, bool HASBIAS>
__global__ __launch_bounds__(256, 1)
void gemm_i8(const i8* __restrict__ A1, const i8* __restrict__ A2, const float* __restrict__ sA,
             const i8* __restrict__ B1, const i8* __restrict__ B2, const float* __restrict__ sB,
             float* __restrict__ Cf, const float* __restrict__ bias, float alpha,
             int Kd, int ldC, long long aRowZ, long long bRowZ, long long cOffZ)
{
    extern __shared__ __align__(128) char smem[];
    const uint32_t sb = s2u(smem);
    const int tid = threadIdx.x, wid = tid >> 5, lane = tid & 31;
    const int wm = wid >> 2, wn = wid & 3;
    const int rowBase = blockIdx.y * 128, colBase = blockIdx.x * 128;
    const long long aRow0 = (long long)blockIdx.z * aRowZ + rowBase;
    const long long bRow0 = (long long)blockIdx.z * bRowZ + colBase;

    const int r = tid >> 1, cg = tid & 1;
    const i8* pA1 = A1 + (aRow0 + r) * (long long)Kd + cg * 16;
    const i8* pA2 = A2 + (aRow0 + r) * (long long)Kd + cg * 16;
    const i8* pB1 = B1 + (bRow0 + r) * (long long)Kd + cg * 16;
    const i8* pB2 = B2 + (bRow0 + r) * (long long)Kd + cg * 16;
    const uint32_t dRow = (uint32_t)(r * ROWB + cg * 16);
    const int nCh = Kd >> 5;

    auto load_stage = [&](int c, int s) {
        const uint32_t d = sb + s * STAGE_SZ + dRow;
        const long long cb = (long long)c * 32;
        CPA16(d + R_A1, pA1 + cb);
        CPA16(d + R_A2, pA2 + cb);
        CPA16(d + R_B1, pB1 + cb);
        CPA16(d + R_B2, pB2 + cb);
        asm volatile("cp.async.commit_group;" ::: "memory");
    };

    const uint32_t aOff = (uint32_t)((wm * 64 + (lane & 7) + ((lane >> 3) & 1) * 8) * ROWB
                                     + (lane >> 4) * 16);
    const uint32_t bOff = (uint32_t)((wn * 32 + (lane & 7) + ((lane >> 3) & 1) * 8) * ROWB
                                     + (lane >> 4) * 16);

    int accP[4][4][4], accQ[4][4][4];
    #pragma unroll
    for (int i = 0; i < 4; i++)
        #pragma unroll
        for (int j = 0; j < 4; j++)
            #pragma unroll
            for (int q = 0; q < 4; q++) { accP[i][j][q] = 0; accQ[i][j][q] = 0; }

    load_stage(0, 0);
    load_stage(1, 1);
    load_stage(2, 2);

    for (int c = 0; c < nCh; c++) {
        const int s = c & (NSTAGE - 1);
        const int rem = nCh - 1 - c;
        if (rem >= 2)      asm volatile("cp.async.wait_group 2;" ::: "memory");
        else if (rem == 1) asm volatile("cp.async.wait_group 1;" ::: "memory");
        else               asm volatile("cp.async.wait_group 0;" ::: "memory");
        __syncthreads();
        if (c + 3 < nCh) load_stage(c + 3, (c + 3) & (NSTAGE - 1));

        const uint32_t st = sb + s * STAGE_SZ;
        uint32_t a1[4][4], a2[4][4], b1[2][4], b2[2][4];
        #pragma unroll
        for (int mt = 0; mt < 4; mt++) {
            LDSM4(a1[mt], st + R_A1 + aOff + mt * (16 * ROWB));
            LDSM4(a2[mt], st + R_A2 + aOff + mt * (16 * ROWB));
        }
        #pragma unroll
        for (int np = 0; np < 2; np++) {
            LDSM4(b1[np], st + R_B1 + bOff + np * (16 * ROWB));
            LDSM4(b2[np], st + R_B2 + bOff + np * (16 * ROWB));
        }
        #pragma unroll
        for (int mt = 0; mt < 4; mt++)
            #pragma unroll
            for (int nt = 0; nt < 4; nt++) {
                const int np = nt >> 1, hi = nt & 1;
                MMAI8(accP[mt][nt], a1[mt], b1[np][hi], b1[np][hi + 2]);
            }
        #pragma unroll
        for (int mt = 0; mt < 4; mt++)
            #pragma unroll
            for (int nt = 0; nt < 4; nt++) {
                const int np = nt >> 1, hi = nt & 1;
                MMAI8(accQ[mt][nt], a1[mt], b2[np][hi], b2[np][hi + 2]);
            }
        #pragma unroll
        for (int mt = 0; mt < 4; mt++)
            #pragma unroll
            for (int nt = 0; nt < 4; nt++) {
                const int np = nt >> 1, hi = nt & 1;
                MMAI8(accQ[mt][nt], a2[mt], b1[np][hi], b1[np][hi + 2]);
            }
    }

    const float* sAz = sA + blockIdx.z * aRowZ + rowBase;
    const float* sBz = sB + blockIdx.z * bRowZ + colBase;

    if (TRANSOUT) {
        __syncthreads();
        float* smtf = reinterpret_cast<float*>(smem);
        #pragma unroll
        for (int mt = 0; mt < 4; mt++)
            #pragma unroll
            for (int h = 0; h < 2; h++) {
                const int mloc = wm * 64 + mt * 16 + h * 8 + (lane >> 2);
                const float sa = alpha * sAz[mloc];
                #pragma unroll
                for (int nt = 0; nt < 4; nt++) {
                    const int nloc = wn * 32 + nt * 8 + (lane & 3) * 2;
                    float c0 = fmaf(65536.f, (float)accP[mt][nt][h*2+0], 256.f*(float)accQ[mt][nt][h*2+0]);
                    float c1 = fmaf(65536.f, (float)accP[mt][nt][h*2+1], 256.f*(float)accQ[mt][nt][h*2+1]);
                    smtf[nloc * 132 + mloc]       = sa * sBz[nloc]     * c0;
                    smtf[(nloc + 1) * 132 + mloc] = sa * sBz[nloc + 1] * c1;
                }
            }
        __syncthreads();
        const int b = rowBase >> 11, seq0 = rowBase & 2047;
        #pragma unroll
        for (int i = 0; i < 16; i++) {
            const int g = tid + i * 256;
            const int n = g >> 5, o = (g & 31) * 4;
            float4 v = *reinterpret_cast<const float4*>(smtf + n * 132 + o);
            *reinterpret_cast<float4*>(Cf
                + ((long long)(b * 1024 + colBase + n)) * 2048 + seq0 + o) = v;
        }
    } else {
        #pragma unroll
        for (int mt = 0; mt < 4; mt++)
            #pragma unroll
            for (int h = 0; h < 2; h++) {
                const int mloc = wm * 64 + mt * 16 + h * 8 + (lane >> 2);
                const float sa = alpha * sAz[mloc];
                const long long rbase = (long long)blockIdx.z * cOffZ
                    + (long long)(rowBase + mloc) * ldC + colBase;
                #pragma unroll
                for (int nt = 0; nt < 4; nt++) {
                    const int nloc = wn * 32 + nt * 8 + (lane & 3) * 2;
                    float c0 = fmaf(65536.f, (float)accP[mt][nt][h*2+0], 256.f*(float)accQ[mt][nt][h*2+0]);
                    float c1 = fmaf(65536.f, (float)accP[mt][nt][h*2+1], 256.f*(float)accQ[mt][nt][h*2+1]);
                    float2 w;
                    w.x = sa * sBz[nloc]     * c0;
                    w.y = sa * sBz[nloc + 1] * c1;
                    if (HASBIAS) { w.x += bias[colBase + nloc]; w.y += bias[colBase + nloc + 1]; }
                    *reinterpret_cast<float2*>(Cf + rbase + nloc) = w;
                }
            }
    }
}

// ---- helpers ----
__device__ __forceinline__ void q2(float x, float inv, i8& o1, i8& o2) {
    float t = x * inv;
    float a1 = rintf(t * 0.00390625f);
    a1 = fminf(fmaxf(a1, -127.f), 127.f);
    float a2 = fminf(fmaxf(rintf(t - 256.f * a1), -127.f), 127.f);
    o1 = (i8)(int)a1; o2 = (i8)(int)a2;
}

__global__ __launch_bounds__(256)
void rowquant(const float* __restrict__ src, i8* __restrict__ d1, i8* __restrict__ d2,
              float* __restrict__ s, int Kd)
{
    const int tid = threadIdx.x;
    const long long base = (long long)blockIdx.x * Kd;
    const float4* src4 = reinterpret_cast<const float4*>(src + base);
    const int n4 = Kd >> 2;
    float mx = 0.f;
    for (int i = tid; i < n4; i += 256) {
        float4 v = src4[i];
        mx = fmaxf(mx, fmaxf(fmaxf(fabsf(v.x), fabsf(v.y)), fmaxf(fabsf(v.z), fabsf(v.w))));
    }
    __shared__ float red[256];
    red[tid] = mx; __syncthreads();
    #pragma unroll
    for (int st = 128; st > 0; st >>= 1) { if (tid < st) red[tid] = fmaxf(red[tid], red[tid+st]); __syncthreads(); }
    const float rowmax = fmaxf(red[0], 1e-30f);
    const float inv = 32512.f / rowmax;
    if (tid == 0) s[blockIdx.x] = rowmax * (1.f / 32512.f);
    char4* o1 = reinterpret_cast<char4*>(d1 + base);
    char4* o2 = reinterpret_cast<char4*>(d2 + base);
    for (int i = tid; i < n4; i += 256) {
        float4 v = src4[i];
        char4 c1, c2;
        q2(v.x, inv, c1.x, c2.x); q2(v.y, inv, c1.y, c2.y);
        q2(v.z, inv, c1.z, c2.z); q2(v.w, inv, c1.w, c2.w);
        o1[i] = c1; o2[i] = c2;
    }
}

__global__ __launch_bounds__(256)
void transpose4(const float* __restrict__ w0, const float* __restrict__ w1,
                const float* __restrict__ w2, const float* __restrict__ w3,
                float* __restrict__ T)
{
    const float* W = blockIdx.z == 0 ? w0 : blockIdx.z == 1 ? w1 : blockIdx.z == 2 ? w2 : w3;
    float* out = T + (size_t)blockIdx.z * DIM * DIM;
    __shared__ float t[32][33];
    int x = blockIdx.x * 32 + threadIdx.x;
    int y0 = blockIdx.y * 32;
    #pragma unroll
    for (int j = threadIdx.y; j < 32; j += 8)
        t[j][threadIdx.x] = W[(long long)(y0 + j) * DIM + x];
    __syncthreads();
    int xo = y0 + threadIdx.x, yo = blockIdx.x * 32;
    #pragma unroll
    for (int j = threadIdx.y; j < 32; j += 8)
        out[(long long)(yo + j) * DIM + xo] = t[threadIdx.x][j];
}

__global__ __launch_bounds__(256)
void softmax_quant(const float* __restrict__ S, i8* __restrict__ P1, i8* __restrict__ P2,
                   float* __restrict__ sP)
{
    const float* row = S + (long long)blockIdx.x * SEQ;
    const int tid = threadIdx.x;
    float v[8], m = -CUDART_INF_F;
    #pragma unroll
    for (int i = 0; i < 8; i++) { v[i] = row[tid + i*256]; m = fmaxf(m, v[i]); }
    __shared__ float red[256];
    red[tid] = m; __syncthreads();
    #pragma unroll
    for (int st = 128; st > 0; st >>= 1) { if (tid < st) red[tid] = fmaxf(red[tid], red[tid+st]); __syncthreads(); }
    m = red[0]; __syncthreads();
    float sum = 0.f;
    #pragma unroll
    for (int i = 0; i < 8; i++) { v[i] = __expf(v[i] - m); sum += v[i]; }
    red[tid] = sum; __syncthreads();
    #pragma unroll
    for (int st = 128; st > 0; st >>= 1) { if (tid < st) red[tid] += red[tid+st]; __syncthreads(); }
    const float inv = 1.0f / red[0];
    if (tid == 0) sP[blockIdx.x] = inv * (1.f / 32512.f);
    const long long base = (long long)blockIdx.x * SEQ;
    #pragma unroll
    for (int i = 0; i < 8; i++) {
        float t = v[i] * 32512.f;
        float a1 = fminf(rintf(t * 0.00390625f), 127.f);
        float a2 = fminf(fmaxf(rintf(t - 256.f * a1), -127.f), 127.f);
        P1[base + tid + i*256] = (i8)(int)a1;
        P2[base + tid + i*256] = (i8)(int)a2;
    }
}

// ---- launch ----
extern "C" void kernel_launch(void* const* d_in, const int* in_sizes, int n_in,
                              void* d_out, int out_size)
{
    const float* X  = (const float*)d_in[0];
    const float* bo = (const float*)d_in[5];
    float* out = (float*)d_out;

    i8 *X1, *X2, *W1, *W2, *Q1, *Q2, *K1, *K2, *V1, *V2, *P1, *P2, *O1, *O2;
    float *sX, *sW, *sQ, *sK, *sV, *sP, *sO, *Wt, *Qf, *Kf, *Vtf, *Sc, *Of;
    cudaGetSymbolAddress((void**)&X1, g_X1); cudaGetSymbolAddress((void**)&X2, g_X2);
    cudaGetSymbolAddress((void**)&sX, g_sX); cudaGetSymbolAddress((void**)&Wt, g_Wt);
    cudaGetSymbolAddress((void**)&W1, g_W1); cudaGetSymbolAddress((void**)&W2, g_W2);
    cudaGetSymbolAddress((void**)&sW, g_sW);
    cudaGetSymbolAddress((void**)&Qf, g_Qf); cudaGetSymbolAddress((void**)&Kf, g_Kf);
    cudaGetSymbolAddress((void**)&Vtf, g_Vtf);
    cudaGetSymbolAddress((void**)&Q1, g_Q1); cudaGetSymbolAddress((void**)&Q2, g_Q2);
    cudaGetSymbolAddress((void**)&sQ, g_sQ);
    cudaGetSymbolAddress((void**)&K1, g_K1); cudaGetSymbolAddress((void**)&K2, g_K2);
    cudaGetSymbolAddress((void**)&sK, g_sK);
    cudaGetSymbolAddress((void**)&V1, g_V1); cudaGetSymbolAddress((void**)&V2, g_V2);
    cudaGetSymbolAddress((void**)&sV, g_sV);
    cudaGetSymbolAddress((void**)&Sc, g_S);
    cudaGetSymbolAddress((void**)&P1, g_P1); cudaGetSymbolAddress((void**)&P2, g_P2);
    cudaGetSymbolAddress((void**)&sP, g_sP);
    cudaGetSymbolAddress((void**)&Of, g_Of);
    cudaGetSymbolAddress((void**)&O1, g_O1); cudaGetSymbolAddress((void**)&O2, g_O2);
    cudaGetSymbolAddress((void**)&sO, g_sO);

    cudaFuncSetAttribute(gemm_i8<false,false>, cudaFuncAttributeMaxDynamicSharedMemorySize, GEMM_SMEM);
    cudaFuncSetAttribute(gemm_i8<false,true >, cudaFuncAttributeMaxDynamicSharedMemorySize, GEMM_SMEM);
    cudaFuncSetAttribute(gemm_i8<true ,false>, cudaFuncAttributeMaxDynamicSharedMemorySize, GEMM_SMEM);

    const size_t wsz = (size_t)DIM * DIM;

    rowquant<<<MTOT, 256>>>(X, X1, X2, sX, DIM);
    transpose4<<<dim3(32,32,4), dim3(32,8)>>>((const float*)d_in[1], (const float*)d_in[2],
                                              (const float*)d_in[3], (const float*)d_in[4], Wt);
    rowquant<<<4*DIM, 256>>>(Wt, W1, W2, sW, DIM);

    {
        dim3 g(DIM/128, MTOT/128, 1);
        gemm_i8<false,false><<<g, 256, GEMM_SMEM>>>(X1, X2, sX, W1, W2, sW,
            Qf, nullptr, 1.f, DIM, DIM, 0, 0, 0);
        gemm_i8<false,false><<<g, 256, GEMM_SMEM>>>(X1, X2, sX, W1+wsz, W2+wsz, sW+DIM,
            Kf, nullptr, 1.f, DIM, DIM, 0, 0, 0);
        gemm_i8<true,false><<<g, 256, GEMM_SMEM>>>(X1, X2, sX, W1+2*wsz, W2+2*wsz, sW+2*DIM,
            Vtf, nullptr, 1.f, DIM, 0, 0, 0, 0);
    }

    rowquant<<<MTOT, 256>>>(Qf, Q1, Q2, sQ, DIM);
    rowquant<<<MTOT, 256>>>(Kf, K1, K2, sK, DIM);
    rowquant<<<BATCH*DIM, 256>>>(Vtf, V1, V2, sV, SEQ);

    {
        dim3 g(SEQ/128, SEQ/128, BATCH);
        gemm_i8<false,false><<<g, 256, GEMM_SMEM>>>(Q1, Q2, sQ, K1, K2, sK,
            Sc, nullptr, 1.f/32.f, DIM, SEQ, SEQ, SEQ, (long long)SEQ*SEQ);
    }

    softmax_quant<<<MTOT, 256>>>(Sc, P1, P2, sP);

    {
        dim3 g(DIM/128, SEQ/128, BATCH);
        gemm_i8<false,false><<<g, 256, GEMM_SMEM>>>(P1, P2, sP, V1, V2, sV,
            Of, nullptr, 1.f, SEQ, DIM, SEQ, DIM, (long long)SEQ*DIM);
    }

    rowquant<<<MTOT, 256>>>(Of, O1, O2, sO, DIM);
    {
        dim3 g(DIM/128, MTOT/128, 1);
        gemm_i8<false,true><<<g, 256, GEMM_SMEM>>>(O1, O2, sO, W1+3*wsz, W2+3*wsz, sW+3*DIM,
            out, bo, 1.f, DIM, DIM, 0, 0, 0);
    }
}

// round 9
// speedup vs baseline: 2.2379x; 2.2379x over previous
#include <cuda_runtime.h>
#include <cuda_bf16.h>
#include <cstdint>
#include <math_constants.h>

constexpr int BATCH = 4, SEQ = 2048, DIM = 1024, MTOT = BATCH * SEQ;

// ---- scratch (device globals; 16B-aligned) ----
__device__ __align__(16) __nv_bfloat16 g_Xhi [(size_t)MTOT * DIM];
__device__ __align__(16) __nv_bfloat16 g_Xlo [(size_t)MTOT * DIM];
__device__ __align__(16) __nv_bfloat16 g_Wth [4][(size_t)DIM * DIM];
__device__ __align__(16) __nv_bfloat16 g_Wtl [4][(size_t)DIM * DIM];
__device__ __align__(16) __nv_bfloat16 g_Qhi [(size_t)MTOT * DIM];
__device__ __align__(16) __nv_bfloat16 g_Qlo [(size_t)MTOT * DIM];
__device__ __align__(16) __nv_bfloat16 g_Khi [(size_t)MTOT * DIM];
__device__ __align__(16) __nv_bfloat16 g_Klo [(size_t)MTOT * DIM];
__device__ __align__(16) __nv_bfloat16 g_Vthi[(size_t)BATCH * DIM * SEQ];
__device__ __align__(16) __nv_bfloat16 g_Vtlo[(size_t)BATCH * DIM * SEQ];
__device__ __align__(16) float         g_S   [(size_t)BATCH * SEQ * SEQ];
__device__ __align__(16) __nv_bfloat16 g_Phi [(size_t)BATCH * SEQ * SEQ];
__device__ __align__(16) __nv_bfloat16 g_Plo [(size_t)BATCH * SEQ * SEQ];
__device__ __align__(16) __nv_bfloat16 g_Ohi [(size_t)MTOT * DIM];
__device__ __align__(16) __nv_bfloat16 g_Olo [(size_t)MTOT * DIM];

__device__ __forceinline__ uint32_t s2u(const void* p) {
    uint32_t a;
    asm("{ .reg .u64 t; cvta.to.shared.u64 t, %1; cvt.u32.u64 %0, t; }" : "=r"(a) : "l"(p));
    return a;
}
#define CPA16(dst, src) \
    asm volatile("cp.async.cg.shared.global [%0], [%1], 16;" :: "r"(dst), "l"(src) : "memory")
#define LDSM4(r, a) \
    asm volatile("ldmatrix.sync.aligned.m8n8.x4.shared.b16 {%0,%1,%2,%3}, [%4];" \
        : "=r"((r)[0]), "=r"((r)[1]), "=r"((r)[2]), "=r"((r)[3]) : "r"(a))
#define MMA16816(c, a, b0, b1) \
    asm volatile("mma.sync.aligned.m16n8k16.row.col.f32.bf16.bf16.f32 " \
        "{%0,%1,%2,%3}, {%4,%5,%6,%7}, {%8,%9}, {%0,%1,%2,%3};" \
        : "+f"((c)[0]), "+f"((c)[1]), "+f"((c)[2]), "+f"((c)[3]) \
        : "r"((a)[0]), "r"((a)[1]), "r"((a)[2]), "r"((a)[3]), "r"(b0), "r"(b1))

// ---- GEMM: D[m][n] = sum_k A[m][k]*B[n][k]; bf16x3 split via mma.sync ----
// CTA 128x128, 16 warps (2x8), warp tile 64x16, K-chunk 32, 4-stage cp.async.
// SMEM rows padded to 80B (conflict-free ldmatrix).
constexpr int ROWB = 80;
constexpr int R_AH = 0, R_AL = 10240, R_BH = 20480, R_BL = 30720;
constexpr int STAGE_SZ = 40960;
constexpr int NSTAGE = 4;
constexpr int GEMM_SMEM = NSTAGE * STAGE_SZ;      // 163840

// MODE 0: fp32 out (alpha, opt bias). MODE 1: bf16 hi/lo out. MODE 2: Vt hi/lo out.
template<int MODE, bool HASBIAS>
__global__ __launch_bounds__(512, 1)
void gemm_mma(const __nv_bfloat16* __restrict__ Ah, const __nv_bfloat16* __restrict__ Al,
              const __nv_bfloat16* __restrict__ Bh, const __nv_bfloat16* __restrict__ Bl,
              float* __restrict__ Cf,
              __nv_bfloat16* __restrict__ Ch, __nv_bfloat16* __restrict__ Cl,
              const float* __restrict__ bias,
              int Kd, int ldC, float alpha,
              long long aRowZ, long long bRowZ, long long cOffZ)
{
    extern __shared__ __align__(128) char smem[];
    const uint32_t sb = s2u(smem);
    const int tid = threadIdx.x, wid = tid >> 5, lane = tid & 31;
    const int wm = wid >> 3, wn = wid & 7;          // 2x8 warp grid
    const int rowBase = blockIdx.y * 128, colBase = blockIdx.x * 128;
    const long long aRow0 = (long long)blockIdx.z * aRowZ + rowBase;
    const long long bRow0 = (long long)blockIdx.z * bRowZ + colBase;

    // cp.async: thread -> (row r=tid/4 in 0..127, granule cg=tid&3); 1 granule/array
    const int r = tid >> 2, cg = tid & 3;
    const long long rowStep = (long long)Kd * 2;
    const char* pAH = (const char*)Ah + (aRow0 + r) * rowStep + cg * 16;
    const char* pAL = (const char*)Al + (aRow0 + r) * rowStep + cg * 16;
    const char* pBH = (const char*)Bh + (bRow0 + r) * rowStep + cg * 16;
    const char* pBL = (const char*)Bl + (bRow0 + r) * rowStep + cg * 16;
    const uint32_t dRow = (uint32_t)(r * ROWB + cg * 16);
    const int nCh = Kd >> 5;

    auto load_stage = [&](int c, int s) {
        const uint32_t d = sb + s * STAGE_SZ + dRow;
        const long long cb = (long long)c * 64;     // 32 bf16 = 64B per chunk
        CPA16(d + R_AH, pAH + cb);
        CPA16(d + R_AL, pAL + cb);
        CPA16(d + R_BH, pBH + cb);
        CPA16(d + R_BL, pBL + cb);
        asm volatile("cp.async.commit_group;" ::: "memory");
    };

    // A frag: m16 x k16 per LDSM4. B frag: n16 x k16 per LDSM4
    // (tiles: r0=(n0-7,k0-7) r1=(n8-15,k0-7) r2=(n0-7,k8-15) r3=(n8-15,k8-15);
    //  mma B pair for n-octet nt: (b[nt], b[nt+2]))
    const uint32_t aOff = (uint32_t)((wm * 64 + (lane & 7) + ((lane >> 3) & 1) * 8) * ROWB
                                     + (lane >> 4) * 16);
    const uint32_t bOff = (uint32_t)((wn * 16 + (lane & 7) + ((lane >> 3) & 1) * 8) * ROWB
                                     + (lane >> 4) * 16);

    float acc[4][2][4];
    #pragma unroll
    for (int i = 0; i < 4; i++)
        #pragma unroll
        for (int j = 0; j < 2; j++)
            #pragma unroll
            for (int q = 0; q < 4; q++) acc[i][j][q] = 0.0f;

    load_stage(0, 0);
    load_stage(1, 1);
    load_stage(2, 2);

    for (int c = 0; c < nCh; c++) {
        const int s = c & (NSTAGE - 1);
        const int rem = nCh - 1 - c;
        if (rem >= 2)      asm volatile("cp.async.wait_group 2;" ::: "memory");
        else if (rem == 1) asm volatile("cp.async.wait_group 1;" ::: "memory");
        else               asm volatile("cp.async.wait_group 0;" ::: "memory");
        __syncthreads();
        if (c + 3 < nCh) load_stage(c + 3, (c + 3) & (NSTAGE - 1));

        const uint32_t st = sb + s * STAGE_SZ;
        #pragma unroll
        for (int k16 = 0; k16 < 2; k16++) {
            uint32_t ah[4][4], al[4][4], bh[4], bl[4];
            #pragma unroll
            for (int mt = 0; mt < 4; mt++) {
                LDSM4(ah[mt], st + R_AH + aOff + mt * (16 * ROWB) + k16 * 32);
                LDSM4(al[mt], st + R_AL + aOff + mt * (16 * ROWB) + k16 * 32);
            }
            LDSM4(bh, st + R_BH + bOff + k16 * 32);
            LDSM4(bl, st + R_BL + bOff + k16 * 32);
            #pragma unroll
            for (int mt = 0; mt < 4; mt++)
                #pragma unroll
                for (int nt = 0; nt < 2; nt++)
                    MMA16816(acc[mt][nt], ah[mt], bh[nt], bh[nt + 2]);
            #pragma unroll
            for (int mt = 0; mt < 4; mt++)
                #pragma unroll
                for (int nt = 0; nt < 2; nt++)
                    MMA16816(acc[mt][nt], ah[mt], bl[nt], bl[nt + 2]);
            #pragma unroll
            for (int mt = 0; mt < 4; mt++)
                #pragma unroll
                for (int nt = 0; nt < 2; nt++)
                    MMA16816(acc[mt][nt], al[mt], bh[nt], bh[nt + 2]);
        }
    }

    // ---- epilogue ----
    if (MODE == 2) {
        // stage fragments into smem as [n][m], then coalesced 16B stores
        const int b = rowBase >> 11;
        const int seq0 = rowBase & 2047;
        const int mloc0 = wm * 64 + (lane >> 2);
        const int nloc0 = wn * 16 + (lane & 3) * 2;
        __nv_bfloat16* smt = reinterpret_cast<__nv_bfloat16*>(smem);
        constexpr int MP = 136;
        #pragma unroll 1
        for (int p = 0; p < 2; p++) {
            __syncthreads();
            #pragma unroll
            for (int mt = 0; mt < 4; mt++)
                #pragma unroll
                for (int nt = 0; nt < 2; nt++)
                    #pragma unroll
                    for (int h = 0; h < 2; h++) {
                        float v0 = acc[mt][nt][h * 2 + 0] * alpha;
                        float v1 = acc[mt][nt][h * 2 + 1] * alpha;
                        __nv_bfloat16 w0, w1;
                        if (p == 0) { w0 = __float2bfloat16(v0); w1 = __float2bfloat16(v1); }
                        else {
                            __nv_bfloat16 h0 = __float2bfloat16(v0), h1 = __float2bfloat16(v1);
                            w0 = __float2bfloat16(v0 - __bfloat162float(h0));
                            w1 = __float2bfloat16(v1 - __bfloat162float(h1));
                        }
                        const int m = mloc0 + mt * 16 + h * 8;
                        const int n = nloc0 + nt * 8;
                        smt[n * MP + m]       = w0;
                        smt[(n + 1) * MP + m] = w1;
                    }
            __syncthreads();
            __nv_bfloat16* dst = p ? Cl : Ch;
            #pragma unroll
            for (int i = 0; i < 4; i++) {
                const int g = tid + i * 512;
                const int n = g >> 4, o = g & 15;
                uint4 val = *reinterpret_cast<const uint4*>(smt + n * MP + o * 8);
                *reinterpret_cast<uint4*>(dst
                    + ((long long)(b * 1024 + colBase + n)) * 2048 + seq0 + o * 8) = val;
            }
        }
    } else {
        const int mBase = rowBase + wm * 64 + (lane >> 2);
        const int nBaseW = colBase + wn * 16 + (lane & 3) * 2;
        #pragma unroll
        for (int mt = 0; mt < 4; mt++)
            #pragma unroll
            for (int nt = 0; nt < 2; nt++) {
                const int n = nBaseW + nt * 8;
                #pragma unroll
                for (int h = 0; h < 2; h++) {
                    const int m = mBase + mt * 16 + h * 8;
                    float v0 = acc[mt][nt][h * 2 + 0] * alpha;
                    float v1 = acc[mt][nt][h * 2 + 1] * alpha;
                    if (MODE == 0) {
                        if (HASBIAS) { v0 += bias[n]; v1 += bias[n + 1]; }
                        float2 w; w.x = v0; w.y = v1;
                        *reinterpret_cast<float2*>(Cf + (long long)blockIdx.z * cOffZ
                            + (long long)m * ldC + n) = w;
                    } else {
                        __nv_bfloat16 h0 = __float2bfloat16(v0), h1 = __float2bfloat16(v1);
                        __nv_bfloat162 hp, lp;
                        hp.x = h0; hp.y = h1;
                        lp.x = __float2bfloat16(v0 - __bfloat162float(h0));
                        lp.y = __float2bfloat16(v1 - __bfloat162float(h1));
                        const long long base = (long long)blockIdx.z * cOffZ
                            + (long long)m * ldC + n;
                        *reinterpret_cast<__nv_bfloat162*>(Ch + base) = hp;
                        *reinterpret_cast<__nv_bfloat162*>(Cl + base) = lp;
                    }
                }
            }
    }
}

// ---- fp32 -> bf16 hi/lo split ----
__global__ __launch_bounds__(256)
void split_kernel(const float4* __restrict__ in, __nv_bfloat162* __restrict__ hi,
                  __nv_bfloat162* __restrict__ lo, int n4)
{
    int i = blockIdx.x * blockDim.x + threadIdx.x;
    if (i >= n4) return;
    float4 v = in[i];
    __nv_bfloat16 hx = __float2bfloat16(v.x), hy = __float2bfloat16(v.y);
    __nv_bfloat16 hz = __float2bfloat16(v.z), hw = __float2bfloat16(v.w);
    __nv_bfloat162 a, b, c, d;
    a.x = hx; a.y = hy; b.x = hz; b.y = hw;
    c.x = __float2bfloat16(v.x - __bfloat162float(hx));
    c.y = __float2bfloat16(v.y - __bfloat162float(hy));
    d.x = __float2bfloat16(v.z - __bfloat162float(hz));
    d.y = __float2bfloat16(v.w - __bfloat162float(hw));
    hi[(size_t)i*2] = a; hi[(size_t)i*2+1] = b;
    lo[(size_t)i*2] = c; lo[(size_t)i*2+1] = d;
}

// ---- all four W[1024][1024] -> Wt hi/lo (transpose + split), z selects ----
__global__ __launch_bounds__(256)
void transpose_split4(const float* __restrict__ w0, const float* __restrict__ w1,
                      const float* __restrict__ w2, const float* __restrict__ w3,
                      __nv_bfloat16* __restrict__ Th, __nv_bfloat16* __restrict__ Tl)
{
    const float* W = blockIdx.z == 0 ? w0 : blockIdx.z == 1 ? w1 : blockIdx.z == 2 ? w2 : w3;
    __nv_bfloat16* oh = Th + (size_t)blockIdx.z * DIM * DIM;
    __nv_bfloat16* ol = Tl + (size_t)blockIdx.z * DIM * DIM;
    __shared__ float t[32][33];
    int x = blockIdx.x * 32 + threadIdx.x;
    int y0 = blockIdx.y * 32;
    #pragma unroll
    for (int j = threadIdx.y; j < 32; j += 8)
        t[j][threadIdx.x] = W[(long long)(y0 + j) * DIM + x];
    __syncthreads();
    int xo = y0 + threadIdx.x, yo = blockIdx.x * 32;
    #pragma unroll
    for (int j = threadIdx.y; j < 32; j += 8) {
        float v = t[threadIdx.x][j];
        __nv_bfloat16 h = __float2bfloat16(v);
        long long idx = (long long)(yo + j) * DIM + xo;
        oh[idx] = h;
        ol[idx] = __float2bfloat16(v - __bfloat162float(h));
    }
}

// ---- softmax over 2048 cols + bf16 hi/lo split of P ----
__global__ __launch_bounds__(256)
void softmax_split_kernel(const float* __restrict__ S,
                          __nv_bfloat16* __restrict__ Ph, __nv_bfloat16* __restrict__ Pl)
{
    const float* row = S + (long long)blockIdx.x * SEQ;
    const int tid = threadIdx.x;
    float v[8], m = -CUDART_INF_F;
    #pragma unroll
    for (int i = 0; i < 8; i++) { v[i] = row[tid + i*256]; m = fmaxf(m, v[i]); }
    __shared__ float red[256];
    red[tid] = m; __syncthreads();
    #pragma unroll
    for (int s = 128; s > 0; s >>= 1) { if (tid < s) red[tid] = fmaxf(red[tid], red[tid+s]); __syncthreads(); }
    m = red[0]; __syncthreads();
    float sum = 0.f;
    #pragma unroll
    for (int i = 0; i < 8; i++) { v[i] = __expf(v[i] - m); sum += v[i]; }
    red[tid] = sum; __syncthreads();
    #pragma unroll
    for (int s = 128; s > 0; s >>= 1) { if (tid < s) red[tid] += red[tid+s]; __syncthreads(); }
    float inv = 1.0f / red[0];
    const long long base = (long long)blockIdx.x * SEQ;
    #pragma unroll
    for (int i = 0; i < 8; i++) {
        float p = v[i] * inv;
        __nv_bfloat16 h = __float2bfloat16(p);
        Ph[base + tid + i*256] = h;
        Pl[base + tid + i*256] = __float2bfloat16(p - __bfloat162float(h));
    }
}

// ---- launch ----
extern "C" void kernel_launch(void* const* d_in, const int* in_sizes, int n_in,
                              void* d_out, int out_size)
{
    const float* X  = (const float*)d_in[0];
    const float* bo = (const float*)d_in[5];
    float* out = (float*)d_out;

    __nv_bfloat16 *Xhi, *Xlo, *Qhi, *Qlo, *Khi, *Klo, *Vthi, *Vtlo, *Phi, *Plo, *Ohi, *Olo;
    __nv_bfloat16 *Wth, *Wtl;
    float* Sc;
    cudaGetSymbolAddress((void**)&Xhi, g_Xhi);   cudaGetSymbolAddress((void**)&Xlo, g_Xlo);
    cudaGetSymbolAddress((void**)&Wth, g_Wth);   cudaGetSymbolAddress((void**)&Wtl, g_Wtl);
    cudaGetSymbolAddress((void**)&Qhi, g_Qhi);   cudaGetSymbolAddress((void**)&Qlo, g_Qlo);
    cudaGetSymbolAddress((void**)&Khi, g_Khi);   cudaGetSymbolAddress((void**)&Klo, g_Klo);
    cudaGetSymbolAddress((void**)&Vthi, g_Vthi); cudaGetSymbolAddress((void**)&Vtlo, g_Vtlo);
    cudaGetSymbolAddress((void**)&Sc, g_S);
    cudaGetSymbolAddress((void**)&Phi, g_Phi);   cudaGetSymbolAddress((void**)&Plo, g_Plo);
    cudaGetSymbolAddress((void**)&Ohi, g_Ohi);   cudaGetSymbolAddress((void**)&Olo, g_Olo);

    cudaFuncSetAttribute(gemm_mma<0,false>, cudaFuncAttributeMaxDynamicSharedMemorySize, GEMM_SMEM);
    cudaFuncSetAttribute(gemm_mma<0,true >, cudaFuncAttributeMaxDynamicSharedMemorySize, GEMM_SMEM);
    cudaFuncSetAttribute(gemm_mma<1,false>, cudaFuncAttributeMaxDynamicSharedMemorySize, GEMM_SMEM);
    cudaFuncSetAttribute(gemm_mma<2,false>, cudaFuncAttributeMaxDynamicSharedMemorySize, GEMM_SMEM);

    const size_t wsz = (size_t)DIM * DIM;

    // 1: X split   2: W transpose+split (single launch)
    split_kernel<<<(MTOT*DIM/4 + 255)/256, 256>>>((const float4*)X,
        (__nv_bfloat162*)Xhi, (__nv_bfloat162*)Xlo, MTOT*DIM/4);
    transpose_split4<<<dim3(32,32,4), dim3(32,8)>>>((const float*)d_in[1], (const float*)d_in[2],
        (const float*)d_in[3], (const float*)d_in[4], Wth, Wtl);

    // 3-5: Q, K, Vt projections
    {
        dim3 g(DIM/128, MTOT/128, 1);
        gemm_mma<1,false><<<g, 512, GEMM_SMEM>>>(Xhi, Xlo, Wth + 0*wsz, Wtl + 0*wsz,
            nullptr, Qhi, Qlo, nullptr, DIM, DIM, 1.0f, 0, 0, 0);
        gemm_mma<1,false><<<g, 512, GEMM_SMEM>>>(Xhi, Xlo, Wth + 1*wsz, Wtl + 1*wsz,
            nullptr, Khi, Klo, nullptr, DIM, DIM, 1.0f, 0, 0, 0);
        gemm_mma<2,false><<<g, 512, GEMM_SMEM>>>(Xhi, Xlo, Wth + 2*wsz, Wtl + 2*wsz,
            nullptr, Vthi, Vtlo, nullptr, DIM, DIM, 1.0f, 0, 0, 0);
    }

    // 6: scores = (Q @ K^T)/32 (captured by ncu -s 5 -c 1)
    {
        dim3 g(SEQ/128, SEQ/128, BATCH);
        gemm_mma<0,false><<<g, 512, GEMM_SMEM>>>(Qhi, Qlo, Khi, Klo,
            Sc, nullptr, nullptr, nullptr, DIM, SEQ, 1.0f/32.0f,
            (long long)SEQ, (long long)SEQ, (long long)SEQ * SEQ);
    }

    // 7: softmax + split -> P hi/lo
    softmax_split_kernel<<<BATCH*SEQ, 256>>>(Sc, Phi, Plo);

    // 8: O = P @ V  (B = Vt K-major, K=2048)
    {
        dim3 g(DIM/128, SEQ/128, BATCH);
        gemm_mma<1,false><<<g, 512, GEMM_SMEM>>>(Phi, Plo, Vthi, Vtlo,
            nullptr, Ohi, Olo, nullptr, SEQ, DIM, 1.0f,
            (long long)SEQ, (long long)DIM, (long long)SEQ * DIM);
    }

    // 9: out = O @ Wo + bo
    {
        dim3 g(DIM/128, MTOT/128, 1);
        gemm_mma<0,true><<<g, 512, GEMM_SMEM>>>(Ohi, Olo, Wth + 3*wsz, Wtl + 3*wsz,
            out, nullptr, nullptr, bo, DIM, DIM, 1.0f, 0, 0, 0);
    }
}